// round 7
// baseline (speedup 1.0000x reference)
#include <cuda_runtime.h>
#include <stdint.h>

#define C_     128
#define HH     112
#define WW     112
#define BATCH  8
#define TAPS   9
#define TABW   512            // 511 valid entries + 1 pad
#define TRIMAX 42             // largest staged stripe: 40 rows + 2 halo
#define TCU    114            // used tile cols (112 + 2 halo)
#define TCW    116            // padded u16 stride (232 B)
#define STRIPS 28             // 4-col strips
#define BANDS  8              // row bands per stripe
#define NTHR   (STRIPS * BANDS)   // 224

// Per-channel, per-tap folded LUT: T[c][tap][t2+255] = lut[|t1|,|t2|]*sign/1000
__device__ float g_table[C_ * TAPS * TABW];

__global__ void build_table_kernel(const float* __restrict__ weight,
                                   const float* __restrict__ lut) {
    int ct  = blockIdx.x;            // (c, tap)
    float w  = weight[ct];
    float t1 = rintf(w * 1000.0f);
    t1 = fminf(fmaxf(t1, -255.0f), 255.0f);
    int   i1 = (int)fabsf(t1);
    float s1 = (t1 > 0.0f) ? 1.0f : ((t1 < 0.0f) ? -1.0f : 0.0f);

    int j = threadIdx.x;             // 512 threads, one entry each
    float v = 0.0f;
    if (j < 511) {
        int t2 = j - 255;
        int i2 = abs(t2);
        bool pos = (s1 > 0.0f && t2 > 0) || (s1 < 0.0f && t2 < 0);
        v = lut[i1 * 256 + i2] * (pos ? 1.0f : -1.0f) * (1.0f / 1000.0f);
    }
    g_table[(size_t)ct * TABW + j] = v;
}

// Accumulate one tap-row (dr) into 4 horizontal outputs from 3 packed idx words.
__device__ __forceinline__ void row_accum(const float* __restrict__ tab, int dr,
                                          uint32_t w0, uint32_t w1, uint32_t w2,
                                          float& o0, float& o1, float& o2, float& o3) {
    int i0 = (int)(w0 & 0xffffu), i1 = (int)(w0 >> 16);
    int i2 = (int)(w1 & 0xffffu), i3 = (int)(w1 >> 16);
    int i4 = (int)(w2 & 0xffffu), i5 = (int)(w2 >> 16);
    const float* t0 = tab + (dr * 3 + 0) * TABW;
    const float* t1 = tab + (dr * 3 + 1) * TABW;
    const float* t2 = tab + (dr * 3 + 2) * TABW;
    o0 += t0[i0] + t1[i1] + t2[i2];
    o1 += t0[i1] + t1[i2] + t2[i3];
    o2 += t0[i2] + t1[i3] + t2[i4];
    o3 += t0[i3] + t1[i4] + t2[i5];
}

// One stripe: stage R+2 tile rows, then each thread does NR rows of 4 outputs.
template <int R>
__device__ __forceinline__ void do_stripe(const float* __restrict__ xp,
                                          float* __restrict__ obase,
                                          const float* __restrict__ tab,
                                          uint16_t* __restrict__ sidx,
                                          int r0, int t, int s, int band, int col0) {
    // Stage idx tile (quantize each pixel once to table index [0,510]).
    for (int e = t; e < (R + 2) * TCU; e += NTHR) {
        int tr = e / TCU;
        int tc = e - tr * TCU;
        int gr = r0 - 1 + tr;
        int gc = tc - 1;
        float v = 0.0f;                    // zero-pad -> idx 255
        if (gr >= 0 && gr < HH && gc >= 0 && gc < WW)
            v = xp[gr * WW + gc];
        float q = fminf(fmaxf(rintf(v), -255.0f), 255.0f);
        sidx[tr * TCW + tc] = (uint16_t)((int)q + 255);
    }
    __syncthreads();

    constexpr int NR = R / BANDS;          // rows per band (5 or 4), even
    int rb = band * NR;

    const uint32_t* sidx32 = (const uint32_t*)sidx;
    const int RW = TCW / 2;                // 58 u32 per tile row
    int base = rb * RW + 2 * s;

    uint32_t a0 = sidx32[base + 0], a1 = sidx32[base + 1], a2 = sidx32[base + 2];
    base += RW;
    uint32_t b0 = sidx32[base + 0], b1 = sidx32[base + 1], b2 = sidx32[base + 2];

    float* op = obase + (r0 + rb) * WW + col0;

    #pragma unroll
    for (int i = 0; i < NR; i++) {
        base += RW;
        uint32_t c0 = sidx32[base + 0], c1 = sidx32[base + 1], c2 = sidx32[base + 2];

        float o0 = 0.0f, o1 = 0.0f, o2 = 0.0f, o3 = 0.0f;
        row_accum(tab, 0, a0, a1, a2, o0, o1, o2, o3);
        row_accum(tab, 1, b0, b1, b2, o0, o1, o2, o3);
        row_accum(tab, 2, c0, c1, c2, o0, o1, o2, o3);

        *(float4*)op = make_float4(o0, o1, o2, o3);
        op += WW;

        a0 = b0; a1 = b1; a2 = b2;
        b0 = c0; b1 = c1; b2 = c2;
    }
    __syncthreads();   // protect sidx before next stripe overwrites it
}

__global__ __launch_bounds__(NTHR, 7) void conv_kernel(const float* __restrict__ x,
                                                       float* __restrict__ out) {
    __shared__ float    tab[TAPS * TABW];        // 18432 B
    __shared__ uint16_t sidx[TRIMAX * TCW];      // 9744 B  (total 28176 B -> 7 blocks/SM)

    int bid = blockIdx.x;                  // (b, c)
    int c   = bid & (C_ - 1);
    int b   = bid >> 7;
    int t   = threadIdx.x;

    // Stage this channel's folded table once (float4 copies).
    {
        const float4* ts4 = (const float4*)(g_table + (size_t)c * TAPS * TABW);
        float4* td4 = (float4*)tab;
        #pragma unroll
        for (int i = t; i < (TAPS * TABW) / 4; i += NTHR)
            td4[i] = ts4[i];
    }

    const float* xp = x + ((size_t)(b * C_ + c)) * (HH * WW);
    float* obase    = out + ((size_t)(b * C_ + c)) * (HH * WW);

    int s    = t % STRIPS;                 // col strip
    int band = t / STRIPS;                 // row band
    int col0 = 4 * s;

    do_stripe<40>(xp, obase, tab, sidx,  0, t, s, band, col0);
    do_stripe<40>(xp, obase, tab, sidx, 40, t, s, band, col0);
    do_stripe<32>(xp, obase, tab, sidx, 80, t, s, band, col0);
}

extern "C" void kernel_launch(void* const* d_in, const int* in_sizes, int n_in,
                              void* d_out, int out_size) {
    const float* x      = (const float*)d_in[0];
    const float* weight = (const float*)d_in[1];
    const float* lut    = (const float*)d_in[2];
    float* out          = (float*)d_out;

    build_table_kernel<<<C_ * TAPS, TABW>>>(weight, lut);
    conv_kernel<<<BATCH * C_, NTHR>>>(x, out);
}

// round 8
// speedup vs baseline: 1.2579x; 1.2579x over previous
#include <cuda_runtime.h>
#include <cuda_fp16.h>
#include <stdint.h>

#define C_     128
#define HH     112
#define WW     112
#define BATCH  8
#define TAPS   9
#define TABW   512            // 511 valid entries + 1 pad
#define SROWS  56             // output rows per stripe
#define TRI    (SROWS + 2)    // 58 staged tile rows
#define TCU    114            // used tile cols (112 + 2 halo)
#define TCW    116            // padded u16 stride (232 B)
#define STRIPS 28             // 4-col strips
#define BANDS  8              // row bands per stripe
#define BROWS  7              // rows per band (8*7 = 56)
#define NTHR   (STRIPS * BANDS)   // 224

// Quad-packed per-channel per-kernel-row table:
// g_tabh[(c*3+dr)*TABW + i] = half4{ T[dr][0][i], T[dr][1][i], T[dr][2][i], 0 }
// where T[dr][dc][i] = lut[|t1|,|i-255|] * sign / 1000 for weight tap (dr,dc).
__device__ uint2 g_tabh[C_ * 3 * TABW];

__global__ void build_table_kernel(const float* __restrict__ weight,
                                   const float* __restrict__ lut) {
    int cd = blockIdx.x;             // (c, dr)
    int c  = cd / 3;
    int dr = cd - 3 * c;
    int j  = threadIdx.x;            // 512 threads, one entry each

    float v[3];
    #pragma unroll
    for (int dc = 0; dc < 3; dc++) {
        float w  = weight[c * 9 + dr * 3 + dc];
        float t1 = rintf(w * 1000.0f);
        t1 = fminf(fmaxf(t1, -255.0f), 255.0f);
        int   i1 = (int)fabsf(t1);
        float s1 = (t1 > 0.0f) ? 1.0f : ((t1 < 0.0f) ? -1.0f : 0.0f);
        float val = 0.0f;
        if (j < 511) {
            int t2 = j - 255;
            int i2 = abs(t2);
            bool pos = (s1 > 0.0f && t2 > 0) || (s1 < 0.0f && t2 < 0);
            val = lut[i1 * 256 + i2] * (pos ? 1.0f : -1.0f) * (1.0f / 1000.0f);
        }
        v[dc] = val;
    }
    __half2 lo = __floats2half2_rn(v[0], v[1]);
    __half2 hi = __floats2half2_rn(v[2], 0.0f);
    uint2 q;
    q.x = *reinterpret_cast<uint32_t*>(&lo);
    q.y = *reinterpret_cast<uint32_t*>(&hi);
    g_tabh[(size_t)cd * TABW + j] = q;
}

__device__ __forceinline__ float h_lo(uint32_t u) {
    __half2 h = *reinterpret_cast<__half2*>(&u);
    return __low2float(h);
}
__device__ __forceinline__ float h_hi(uint32_t u) {
    __half2 h = *reinterpret_cast<__half2*>(&u);
    return __high2float(h);
}

// One kernel-row: 6 quad gathers cover 4 outputs x 3 taps.
// o_j += t0[i_j] + t1[i_{j+1}] + t2[i_{j+2}]
__device__ __forceinline__ void row_accum(const uint2* __restrict__ tabr,
                                          uint32_t w0, uint32_t w1, uint32_t w2,
                                          float& o0, float& o1, float& o2, float& o3) {
    int i0 = (int)(w0 & 0xffffu), i1 = (int)(w0 >> 16);
    int i2 = (int)(w1 & 0xffffu), i3 = (int)(w1 >> 16);
    int i4 = (int)(w2 & 0xffffu), i5 = (int)(w2 >> 16);
    uint2 q0 = tabr[i0], q1 = tabr[i1], q2 = tabr[i2];
    uint2 q3 = tabr[i3], q4 = tabr[i4], q5 = tabr[i5];
    o0 += h_lo(q0.x) + h_hi(q1.x) + h_lo(q2.y);
    o1 += h_lo(q1.x) + h_hi(q2.x) + h_lo(q3.y);
    o2 += h_lo(q2.x) + h_hi(q3.x) + h_lo(q4.y);
    o3 += h_lo(q3.x) + h_hi(q4.x) + h_lo(q5.y);
}

__global__ __launch_bounds__(NTHR, 8) void conv_kernel(const float* __restrict__ x,
                                                       float* __restrict__ out) {
    __shared__ uint2    tabh[3 * TABW];          // 12288 B
    __shared__ uint16_t sidx[TRI * TCW];         // 13456 B  (total 25744 B -> 8 blocks/SM)

    int bid = blockIdx.x;                  // (b, c)
    int c   = bid & (C_ - 1);
    int b   = bid >> 7;
    int t   = threadIdx.x;

    // Stage this channel's quad table once (uint4 copies).
    {
        const uint4* ts4 = (const uint4*)(g_tabh + (size_t)c * 3 * TABW);
        uint4* td4 = (uint4*)tabh;
        #pragma unroll
        for (int i = t; i < (3 * TABW) / 2; i += NTHR)
            td4[i] = ts4[i];
    }

    const float* xp = x + ((size_t)(b * C_ + c)) * (HH * WW);
    float* obase    = out + ((size_t)(b * C_ + c)) * (HH * WW);

    int s    = t % STRIPS;                 // col strip
    int band = t / STRIPS;                 // row band
    int col0 = 4 * s;

    #pragma unroll
    for (int stripe = 0; stripe < 2; stripe++) {
        int r0 = stripe * SROWS;

        // Stage idx tile (quantize each pixel once to table index [0,510]).
        for (int e = t; e < TRI * TCU; e += NTHR) {
            int tr = e / TCU;
            int tc = e - tr * TCU;
            int gr = r0 - 1 + tr;
            int gc = tc - 1;
            float v = 0.0f;                    // zero-pad -> idx 255
            if (gr >= 0 && gr < HH && gc >= 0 && gc < WW)
                v = xp[gr * WW + gc];
            float q = fminf(fmaxf(rintf(v), -255.0f), 255.0f);
            sidx[tr * TCW + tc] = (uint16_t)((int)q + 255);
        }
        __syncthreads();

        // Thread = one 4-col strip in one 7-row band. Rolling packed idx regs.
        int rb = band * BROWS;

        const uint32_t* sidx32 = (const uint32_t*)sidx;
        const int RW = TCW / 2;                // 58 u32 per tile row
        int base = rb * RW + 2 * s;

        uint32_t a0 = sidx32[base + 0], a1 = sidx32[base + 1], a2 = sidx32[base + 2];
        base += RW;
        uint32_t b0 = sidx32[base + 0], b1 = sidx32[base + 1], b2 = sidx32[base + 2];

        float* op = obase + (r0 + rb) * WW + col0;

        #pragma unroll
        for (int i = 0; i < BROWS; i++) {
            base += RW;
            uint32_t c0 = sidx32[base + 0], c1 = sidx32[base + 1], c2 = sidx32[base + 2];

            float o0 = 0.0f, o1 = 0.0f, o2 = 0.0f, o3 = 0.0f;
            row_accum(tabh + 0 * TABW, a0, a1, a2, o0, o1, o2, o3);
            row_accum(tabh + 1 * TABW, b0, b1, b2, o0, o1, o2, o3);
            row_accum(tabh + 2 * TABW, c0, c1, c2, o0, o1, o2, o3);

            *(float4*)op = make_float4(o0, o1, o2, o3);
            op += WW;

            a0 = b0; a1 = b1; a2 = b2;
            b0 = c0; b1 = c1; b2 = c2;
        }
        __syncthreads();   // protect sidx before next stripe overwrites it
    }
}

extern "C" void kernel_launch(void* const* d_in, const int* in_sizes, int n_in,
                              void* d_out, int out_size) {
    const float* x      = (const float*)d_in[0];
    const float* weight = (const float*)d_in[1];
    const float* lut    = (const float*)d_in[2];
    float* out          = (float*)d_out;

    build_table_kernel<<<C_ * 3, TABW>>>(weight, lut);
    conv_kernel<<<BATCH * C_, NTHR>>>(x, out);
}

// round 9
// speedup vs baseline: 1.2642x; 1.0050x over previous
#include <cuda_runtime.h>
#include <cuda_fp16.h>
#include <stdint.h>

#define C_     128
#define HH     112
#define WW     112
#define BATCH  8
#define TABW   512            // 511 valid entries + 1 pad
#define NTHR   224            // 7 warps; warp = 16 rows; lane<28 = 4 cols

// Quad-packed per-channel per-kernel-row table:
// g_tabh[(c*3+dr)*TABW + i] = half4{ T[dr][0][i], T[dr][1][i], T[dr][2][i], 0 }
__device__ uint2 g_tabh[C_ * 3 * TABW];

__global__ void build_table_kernel(const float* __restrict__ weight,
                                   const float* __restrict__ lut) {
    int cd = blockIdx.x;             // (c, dr)
    int c  = cd / 3;
    int dr = cd - 3 * c;
    int j  = threadIdx.x;            // 512 threads, one entry each

    float v[3];
    #pragma unroll
    for (int dc = 0; dc < 3; dc++) {
        float w  = weight[c * 9 + dr * 3 + dc];
        float t1 = rintf(w * 1000.0f);
        t1 = fminf(fmaxf(t1, -255.0f), 255.0f);
        int   i1 = (int)fabsf(t1);
        float s1 = (t1 > 0.0f) ? 1.0f : ((t1 < 0.0f) ? -1.0f : 0.0f);
        float val = 0.0f;
        if (j < 511) {
            int t2 = j - 255;
            int i2 = abs(t2);
            bool pos = (s1 > 0.0f && t2 > 0) || (s1 < 0.0f && t2 < 0);
            val = lut[i1 * 256 + i2] * (pos ? 1.0f : -1.0f) * (1.0f / 1000.0f);
        }
        v[dc] = val;
    }
    __half2 lo = __floats2half2_rn(v[0], v[1]);
    __half2 hi = __floats2half2_rn(v[2], 0.0f);
    uint2 q;
    q.x = *reinterpret_cast<uint32_t*>(&lo);
    q.y = *reinterpret_cast<uint32_t*>(&hi);
    g_tabh[(size_t)cd * TABW + j] = q;
}

__device__ __forceinline__ float h_lo(uint32_t u) {
    __half2 h = *reinterpret_cast<__half2*>(&u);
    return __low2float(h);
}
__device__ __forceinline__ float h_hi(uint32_t u) {
    __half2 h = *reinterpret_cast<__half2*>(&u);
    return __high2float(h);
}

// One tap-row: 6 quad gathers -> 4 outputs. Indices: hl, i0..i3 (packed), hr.
__device__ __forceinline__ void row_accum(const uint2* __restrict__ tabr,
                                          uint32_t w01, uint32_t w23,
                                          uint32_t hl, uint32_t hr,
                                          float& o0, float& o1, float& o2, float& o3) {
    int i0 = (int)(w01 & 0xffffu), i1 = (int)(w01 >> 16);
    int i2 = (int)(w23 & 0xffffu), i3 = (int)(w23 >> 16);
    uint2 qh = tabr[hl], q0 = tabr[i0], q1 = tabr[i1];
    uint2 q2 = tabr[i2], q3 = tabr[i3], qr = tabr[hr];
    o0 += h_lo(qh.x) + h_hi(q0.x) + h_lo(q1.y);
    o1 += h_lo(q0.x) + h_hi(q1.x) + h_lo(q2.y);
    o2 += h_lo(q1.x) + h_hi(q2.x) + h_lo(q3.y);
    o3 += h_lo(q2.x) + h_hi(q3.x) + h_lo(qr.y);
}

__device__ __forceinline__ float4 ldrow(const float* __restrict__ xp, int r, int col, bool act) {
    if (act && r >= 0 && r < HH)
        return *(const float4*)(xp + r * WW + col);
    return make_float4(0.0f, 0.0f, 0.0f, 0.0f);
}

__device__ __forceinline__ void quant(float4 v, uint32_t& w01, uint32_t& w23) {
    int i0 = (int)fminf(fmaxf(rintf(v.x), -255.0f), 255.0f) + 255;
    int i1 = (int)fminf(fmaxf(rintf(v.y), -255.0f), 255.0f) + 255;
    int i2 = (int)fminf(fmaxf(rintf(v.z), -255.0f), 255.0f) + 255;
    int i3 = (int)fminf(fmaxf(rintf(v.w), -255.0f), 255.0f) + 255;
    w01 = (uint32_t)i0 | ((uint32_t)i1 << 16);
    w23 = (uint32_t)i2 | ((uint32_t)i3 << 16);
}

// Halos for a quantized row: hl = left lane's i3, hr = right lane's i0.
__device__ __forceinline__ void halos(uint32_t w01, uint32_t w23, int lane,
                                      uint32_t& hl, uint32_t& hr) {
    hl = __shfl_up_sync(0xffffffffu, w23, 1) >> 16;
    if (lane == 0) hl = 255u;               // col -1 -> zero-pad idx
    hr = __shfl_down_sync(0xffffffffu, w01, 1) & 0xffffu;
    // lane 27's right comes from lane 28, whose zero-load quantizes to 255. OK.
}

__global__ __launch_bounds__(NTHR, 7) void conv_kernel(const float* __restrict__ x,
                                                       float* __restrict__ out) {
    __shared__ uint2 tabh[3 * TABW];             // 12288 B

    int bid = blockIdx.x;                  // (b, c)
    int c   = bid & (C_ - 1);
    int b   = bid >> 7;
    int t   = threadIdx.x;

    // Stage this channel's quad table once.
    {
        const uint4* ts4 = (const uint4*)(g_tabh + (size_t)c * 3 * TABW);
        uint4* td4 = (uint4*)tabh;
        #pragma unroll
        for (int i = t; i < (3 * TABW) / 2; i += NTHR)
            td4[i] = ts4[i];
    }
    __syncthreads();

    int warp = t >> 5;
    int lane = t & 31;
    bool act = lane < 28;
    int col  = 4 * lane;
    int rb   = warp * 16;                  // 7 warps x 16 rows = 112

    const float* xp = x + ((size_t)(b * C_ + c)) * (HH * WW);
    float* obase    = out + ((size_t)(b * C_ + c)) * (HH * WW);

    // Prime rows A = rb-1, B = rb; prefetch row rb+1.
    uint32_t wA01, wA23, hlA, hrA, wB01, wB23, hlB, hrB;
    {
        float4 fA = ldrow(xp, rb - 1, col, act);
        quant(fA, wA01, wA23);
        halos(wA01, wA23, lane, hlA, hrA);
        float4 fB = ldrow(xp, rb, col, act);
        quant(fB, wB01, wB23);
        halos(wB01, wB23, lane, hlB, hrB);
    }
    float4 fN = ldrow(xp, rb + 1, col, act);

    #pragma unroll 4
    for (int i = 0; i < 16; i++) {
        int r = rb + i;
        float4 fC = fN;
        fN = ldrow(xp, r + 2, col, act);   // software-pipelined next row

        uint32_t wC01, wC23, hlC, hrC;
        quant(fC, wC01, wC23);
        halos(wC01, wC23, lane, hlC, hrC);

        if (act) {
            float o0 = 0.0f, o1 = 0.0f, o2 = 0.0f, o3 = 0.0f;
            row_accum(tabh + 0 * TABW, wA01, wA23, hlA, hrA, o0, o1, o2, o3);
            row_accum(tabh + 1 * TABW, wB01, wB23, hlB, hrB, o0, o1, o2, o3);
            row_accum(tabh + 2 * TABW, wC01, wC23, hlC, hrC, o0, o1, o2, o3);
            *(float4*)(obase + r * WW + col) = make_float4(o0, o1, o2, o3);
        }

        wA01 = wB01; wA23 = wB23; hlA = hlB; hrA = hrB;
        wB01 = wC01; wB23 = wC23; hlB = hlC; hrB = hrC;
    }
}

extern "C" void kernel_launch(void* const* d_in, const int* in_sizes, int n_in,
                              void* d_out, int out_size) {
    const float* x      = (const float*)d_in[0];
    const float* weight = (const float*)d_in[1];
    const float* lut    = (const float*)d_in[2];
    float* out          = (float*)d_out;

    build_table_kernel<<<C_ * 3, TABW>>>(weight, lut);
    conv_kernel<<<BATCH * C_, NTHR>>>(x, out);
}

// round 10
// speedup vs baseline: 1.3436x; 1.0628x over previous
#include <cuda_runtime.h>
#include <cuda_fp16.h>
#include <stdint.h>

#define C_     128
#define HH     112
#define WW     112
#define BATCH  8
#define TABW   512            // 511 valid entries + 1 pad
#define NTHR   256            // 8 warps; warp = 14 rows; lane<28 = 4 cols

// Per-channel packed tables:
// g_tab8[c*512+i] = half8 {t00,t01,t02,t10,t11,t12,t20,t21} for index i
// g_tab1[c*512+i] = float t22
// where t_{dr,dc}[i] = lut[|t1(dr,dc)|, |i-255|] * sign / 1000.
__device__ uint4 g_tab8[C_ * TABW];
__device__ float g_tab1[C_ * TABW];

__global__ void build_table_kernel(const float* __restrict__ weight,
                                   const float* __restrict__ lut) {
    int c = blockIdx.x;
    int j = threadIdx.x;             // 512 threads, one entry each

    float v[9];
    #pragma unroll
    for (int k = 0; k < 9; k++) {
        float w  = weight[c * 9 + k];
        float t1 = rintf(w * 1000.0f);
        t1 = fminf(fmaxf(t1, -255.0f), 255.0f);
        int   i1 = (int)fabsf(t1);
        float s1 = (t1 > 0.0f) ? 1.0f : ((t1 < 0.0f) ? -1.0f : 0.0f);
        float val = 0.0f;
        if (j < 511) {
            int t2 = j - 255;
            int i2 = abs(t2);
            bool pos = (s1 > 0.0f && t2 > 0) || (s1 < 0.0f && t2 < 0);
            val = lut[i1 * 256 + i2] * (pos ? 1.0f : -1.0f) * (1.0f / 1000.0f);
        }
        v[k] = val;
    }
    __half2 p0 = __floats2half2_rn(v[0], v[1]);
    __half2 p1 = __floats2half2_rn(v[2], v[3]);
    __half2 p2 = __floats2half2_rn(v[4], v[5]);
    __half2 p3 = __floats2half2_rn(v[6], v[7]);
    uint4 q;
    q.x = *reinterpret_cast<uint32_t*>(&p0);
    q.y = *reinterpret_cast<uint32_t*>(&p1);
    q.z = *reinterpret_cast<uint32_t*>(&p2);
    q.w = *reinterpret_cast<uint32_t*>(&p3);
    g_tab8[(size_t)c * TABW + j] = q;
    g_tab1[(size_t)c * TABW + j] = v[8];
}

__device__ __forceinline__ float h_lo(uint32_t u) {
    __half2 h = *reinterpret_cast<__half2*>(&u);
    return __low2float(h);
}
__device__ __forceinline__ float h_hi(uint32_t u) {
    __half2 h = *reinterpret_cast<__half2*>(&u);
    return __high2float(h);
}

__device__ __forceinline__ float4 ldrow(const float* __restrict__ xp, int r, int col, bool act) {
    if (act && r >= 0 && r < HH)
        return *(const float4*)(xp + r * WW + col);
    return make_float4(0.0f, 0.0f, 0.0f, 0.0f);
}

__device__ __forceinline__ void quant(float4 v, uint32_t& w01, uint32_t& w23) {
    int i0 = (int)fminf(fmaxf(rintf(v.x), -255.0f), 255.0f) + 255;
    int i1 = (int)fminf(fmaxf(rintf(v.y), -255.0f), 255.0f) + 255;
    int i2 = (int)fminf(fmaxf(rintf(v.z), -255.0f), 255.0f) + 255;
    int i3 = (int)fminf(fmaxf(rintf(v.w), -255.0f), 255.0f) + 255;
    w01 = (uint32_t)i0 | ((uint32_t)i1 << 16);
    w23 = (uint32_t)i2 | ((uint32_t)i3 << 16);
}

__device__ __forceinline__ void halos(uint32_t w01, uint32_t w23, int lane,
                                      uint32_t& hl, uint32_t& hr) {
    hl = __shfl_up_sync(0xffffffffu, w23, 1) >> 16;
    if (lane == 0) hl = 255u;               // col -1 -> zero-pad idx
    hr = __shfl_down_sync(0xffffffffu, w01, 1) & 0xffffu;
    // lane 27's hr comes from lane 28 whose zero row quantizes to 255 (pad). OK.
}

// One idx row: 6 LDS.128 + 4 LDS.32 gathers -> three 4-wide partial sums.
// q[k] = entry for index position k-1 (q0=hl, q1..q4 = i0..i3, q5=hr).
// P0_j = t00[q_j]+t01[q_{j+1}]+t02[q_{j+2}]  (contributes to out row z+1)
// P1_j = t10[q_j]+t11[q_{j+1}]+t12[q_{j+2}]  (out row z)
// P2_j = t20[q_j]+t21[q_{j+1}]+t22[q_{j+2}]  (out row z-1)
__device__ __forceinline__ void gather_row(const uint4* __restrict__ tab8,
                                           const float* __restrict__ tab1,
                                           uint32_t w01, uint32_t w23,
                                           uint32_t hl, uint32_t hr,
                                           float4& P0, float4& P1, float4& P2) {
    int i0 = (int)(w01 & 0xffffu), i1 = (int)(w01 >> 16);
    int i2 = (int)(w23 & 0xffffu), i3 = (int)(w23 >> 16);
    uint4 g0 = tab8[hl], g1 = tab8[i0], g2 = tab8[i1];
    uint4 g3 = tab8[i2], g4 = tab8[i3], g5 = tab8[hr];
    float f0 = tab1[i1], f1 = tab1[i2], f2 = tab1[i3], f3 = tab1[hr];

    P0.x = h_lo(g0.x) + h_hi(g1.x) + h_lo(g2.y);
    P0.y = h_lo(g1.x) + h_hi(g2.x) + h_lo(g3.y);
    P0.z = h_lo(g2.x) + h_hi(g3.x) + h_lo(g4.y);
    P0.w = h_lo(g3.x) + h_hi(g4.x) + h_lo(g5.y);

    P1.x = h_hi(g0.y) + h_lo(g1.z) + h_hi(g2.z);
    P1.y = h_hi(g1.y) + h_lo(g2.z) + h_hi(g3.z);
    P1.z = h_hi(g2.y) + h_lo(g3.z) + h_hi(g4.z);
    P1.w = h_hi(g3.y) + h_lo(g4.z) + h_hi(g5.z);

    P2.x = h_lo(g0.w) + h_hi(g1.w) + f0;
    P2.y = h_lo(g1.w) + h_hi(g2.w) + f1;
    P2.z = h_lo(g2.w) + h_hi(g3.w) + f2;
    P2.w = h_lo(g3.w) + h_hi(g4.w) + f3;
}

__global__ __launch_bounds__(NTHR, 5) void conv_kernel(const float* __restrict__ x,
                                                       float* __restrict__ out) {
    __shared__ uint4 tab8[TABW];                 // 8192 B
    __shared__ float tab1[TABW];                 // 2048 B

    int bid = blockIdx.x;                  // (b, c)
    int c   = bid & (C_ - 1);
    int b   = bid >> 7;
    int t   = threadIdx.x;

    // Stage this channel's tables once.
    {
        const uint4* ts = g_tab8 + (size_t)c * TABW;
        const float* fs = g_tab1 + (size_t)c * TABW;
        #pragma unroll
        for (int i = t; i < TABW; i += NTHR) {
            tab8[i] = ts[i];
            tab1[i] = fs[i];
        }
    }
    __syncthreads();

    int warp = t >> 5;
    int lane = t & 31;
    bool act = lane < 28;
    int col  = 4 * lane;
    int rb   = warp * 14;                  // 8 warps x 14 rows = 112

    const float* xp = x + ((size_t)(b * C_ + c)) * (HH * WW);
    float* obase    = out + ((size_t)(b * C_ + c)) * (HH * WW);

    uint32_t w01, w23, hl, hr;
    float4 P0a, P0b, P1b, Pt0, Pt1, Pt2;

    float4 fcur = ldrow(xp, rb - 1, col, act);
    float4 fnext = ldrow(xp, rb, col, act);

    // Peel z = rb-1: only P0 survives.
    quant(fcur, w01, w23);
    halos(w01, w23, lane, hl, hr);
    gather_row(tab8, tab1, w01, w23, hl, hr, Pt0, Pt1, Pt2);
    P0a = Pt0;

    // Peel z = rb: P0, P1 survive.
    fcur = fnext;
    fnext = ldrow(xp, rb + 1, col, act);
    quant(fcur, w01, w23);
    halos(w01, w23, lane, hl, hr);
    gather_row(tab8, tab1, w01, w23, hl, hr, Pt0, Pt1, Pt2);
    P0b = Pt0;
    P1b = Pt1;

    float* op = obase + rb * WW + col;

    #pragma unroll 2
    for (int i = 0; i < 14; i++) {
        // z = rb+1+i arrives; emit out row rb+i.
        fcur = fnext;
        fnext = ldrow(xp, rb + 2 + i, col, act);
        quant(fcur, w01, w23);
        halos(w01, w23, lane, hl, hr);
        gather_row(tab8, tab1, w01, w23, hl, hr, Pt0, Pt1, Pt2);

        if (act) {
            float4 o;
            o.x = P0a.x + P1b.x + Pt2.x;
            o.y = P0a.y + P1b.y + Pt2.y;
            o.z = P0a.z + P1b.z + Pt2.z;
            o.w = P0a.w + P1b.w + Pt2.w;
            *(float4*)op = o;
        }
        op += WW;

        P0a = P0b; P0b = Pt0; P1b = Pt1;
    }
}

extern "C" void kernel_launch(void* const* d_in, const int* in_sizes, int n_in,
                              void* d_out, int out_size) {
    const float* x      = (const float*)d_in[0];
    const float* weight = (const float*)d_in[1];
    const float* lut    = (const float*)d_in[2];
    float* out          = (float*)d_out;

    build_table_kernel<<<C_, TABW>>>(weight, lut);
    conv_kernel<<<BATCH * C_, NTHR>>>(x, out);
}

// round 11
// speedup vs baseline: 1.4157x; 1.0537x over previous
#include <cuda_runtime.h>
#include <cuda_fp16.h>
#include <stdint.h>

#define C_     128
#define HH     112
#define WW     112
#define BATCH  8
#define TABW   512            // 511 valid entries + 1 pad (255 = zero-pixel)
#define NTHR   224            // 7 warps; warp = 16 out rows; lane<28 = 4 cols

// Per-channel packed tables:
// g_tab8[c*512+i] = half8 {t00,t01,t02,t10,t11,t12,t20,t21} for index i
// g_tab1[c*512+i] = float t22
__device__ uint4 g_tab8[C_ * TABW];
__device__ float g_tab1[C_ * TABW];

__global__ void build_table_kernel(const float* __restrict__ weight,
                                   const float* __restrict__ lut) {
    int c = blockIdx.x;
    int j = threadIdx.x;             // 512 threads, one entry each

    float v[9];
    #pragma unroll
    for (int k = 0; k < 9; k++) {
        float w  = weight[c * 9 + k];
        float t1 = rintf(w * 1000.0f);
        t1 = fminf(fmaxf(t1, -255.0f), 255.0f);
        int   i1 = (int)fabsf(t1);
        float s1 = (t1 > 0.0f) ? 1.0f : ((t1 < 0.0f) ? -1.0f : 0.0f);
        float val = 0.0f;
        if (j < 511) {
            int t2 = j - 255;
            int i2 = abs(t2);
            bool pos = (s1 > 0.0f && t2 > 0) || (s1 < 0.0f && t2 < 0);
            val = lut[i1 * 256 + i2] * (pos ? 1.0f : -1.0f) * (1.0f / 1000.0f);
        }
        v[k] = val;
    }
    __half2 p0 = __floats2half2_rn(v[0], v[1]);
    __half2 p1 = __floats2half2_rn(v[2], v[3]);
    __half2 p2 = __floats2half2_rn(v[4], v[5]);
    __half2 p3 = __floats2half2_rn(v[6], v[7]);
    uint4 q;
    q.x = *reinterpret_cast<uint32_t*>(&p0);
    q.y = *reinterpret_cast<uint32_t*>(&p1);
    q.z = *reinterpret_cast<uint32_t*>(&p2);
    q.w = *reinterpret_cast<uint32_t*>(&p3);
    g_tab8[(size_t)c * TABW + j] = q;
    g_tab1[(size_t)c * TABW + j] = v[8];
}

__device__ __forceinline__ float h_lo(uint32_t u) {
    __half2 h = *reinterpret_cast<__half2*>(&u);
    return __low2float(h);
}
__device__ __forceinline__ float h_hi(uint32_t u) {
    __half2 h = *reinterpret_cast<__half2*>(&u);
    return __high2float(h);
}

__device__ __forceinline__ float4 ldrow(const float* __restrict__ xp, int r, int col, bool act) {
    if (act && r >= 0 && r < HH)
        return *(const float4*)(xp + r * WW + col);
    return make_float4(0.0f, 0.0f, 0.0f, 0.0f);
}

// One idx row z: 4 LDS.128 + 4 LDS.32 gathers, halos via value-shuffle.
// Yields three 4-wide partial rows: P0 -> out z+1, P1 -> out z, P2 -> out z-1.
__device__ __forceinline__ void proc_row(const uint4* __restrict__ tab8,
                                         const float* __restrict__ tab1,
                                         uint4 g_pad, int lane, float4 f,
                                         float4& P0, float4& P1, float4& P2) {
    int i0 = (int)fminf(fmaxf(rintf(f.x), -255.0f), 255.0f) + 255;
    int i1 = (int)fminf(fmaxf(rintf(f.y), -255.0f), 255.0f) + 255;
    int i2 = (int)fminf(fmaxf(rintf(f.z), -255.0f), 255.0f) + 255;
    int i3 = (int)fminf(fmaxf(rintf(f.w), -255.0f), 255.0f) + 255;

    // hr index (right halo) for the t22 scalar gather.
    uint32_t hr = (uint32_t)__shfl_down_sync(0xffffffffu, i0, 1);
    // lane 27's source (lane 28) quantized a zero row -> 255 (pad). OK.

    uint4 g1 = tab8[i0], g2 = tab8[i1], g3 = tab8[i2], g4 = tab8[i3];
    float f0 = tab1[i1], f1 = tab1[i2], f2 = tab1[i3], f3 = tab1[hr];

    // Left halo entry g0 = left lane's g4 (3 words needed).
    uint32_t s4x = __shfl_up_sync(0xffffffffu, g4.x, 1);
    uint32_t s4y = __shfl_up_sync(0xffffffffu, g4.y, 1);
    uint32_t s4w = __shfl_up_sync(0xffffffffu, g4.w, 1);
    if (lane == 0) { s4x = g_pad.x; s4y = g_pad.y; s4w = g_pad.w; }
    // Right halo entry g5 = right lane's g1 (2 words needed).
    uint32_t s1y = __shfl_down_sync(0xffffffffu, g1.y, 1);
    uint32_t s1z = __shfl_down_sync(0xffffffffu, g1.z, 1);
    // lane 27 receives lane 28's pad gathers (idx 255). OK.

    P0.x = h_lo(s4x)  + h_hi(g1.x) + h_lo(g2.y);
    P0.y = h_lo(g1.x) + h_hi(g2.x) + h_lo(g3.y);
    P0.z = h_lo(g2.x) + h_hi(g3.x) + h_lo(g4.y);
    P0.w = h_lo(g3.x) + h_hi(g4.x) + h_lo(s1y);

    P1.x = h_hi(s4y)  + h_lo(g1.z) + h_hi(g2.z);
    P1.y = h_hi(g1.y) + h_lo(g2.z) + h_hi(g3.z);
    P1.z = h_hi(g2.y) + h_lo(g3.z) + h_hi(g4.z);
    P1.w = h_hi(g3.y) + h_lo(g4.z) + h_hi(s1z);

    P2.x = h_lo(s4w)  + h_hi(g1.w) + f0;
    P2.y = h_lo(g1.w) + h_hi(g2.w) + f1;
    P2.z = h_lo(g2.w) + h_hi(g3.w) + f2;
    P2.w = h_lo(g3.w) + h_hi(g4.w) + f3;
}

__global__ __launch_bounds__(NTHR, 7) void conv_kernel(const float* __restrict__ x,
                                                       float* __restrict__ out) {
    __shared__ uint4 tab8[TABW];                 // 8192 B
    __shared__ float tab1[TABW];                 // 2048 B

    int bid = blockIdx.x;                  // (b, c)
    int c   = bid & (C_ - 1);
    int b   = bid >> 7;
    int t   = threadIdx.x;

    // Stage this channel's tables once.
    {
        const uint4* ts = g_tab8 + (size_t)c * TABW;
        const float* fs = g_tab1 + (size_t)c * TABW;
        #pragma unroll
        for (int i = t; i < TABW; i += NTHR) {
            tab8[i] = ts[i];
            tab1[i] = fs[i];
        }
    }
    __syncthreads();

    int warp = t >> 5;
    int lane = t & 31;
    bool act = lane < 28;
    int col  = 4 * lane;
    int rb   = warp * 16;                  // 7 warps x 16 rows = 112

    const float* xp = x + ((size_t)(b * C_ + c)) * (HH * WW);
    float* obase    = out + ((size_t)(b * C_ + c)) * (HH * WW);

    uint4 g_pad = tab8[255];               // zero-pixel entry (uniform)

    float4 P0, P1, P2;
    float4 accA = make_float4(0.f, 0.f, 0.f, 0.f);
    float4 accB = make_float4(0.f, 0.f, 0.f, 0.f);

    float4 fcur  = ldrow(xp, rb - 1, col, act);
    float4 fnext = ldrow(xp, rb, col, act);

    // Peel z = rb-1: accB = P0.
    proc_row(tab8, tab1, g_pad, lane, fcur, P0, P1, P2);
    accB = P0;

    // Peel z = rb: accA = accB + P1; accB = P0. (out[rb-1] not ours)
    fcur = fnext;
    fnext = ldrow(xp, rb + 1, col, act);
    proc_row(tab8, tab1, g_pad, lane, fcur, P0, P1, P2);
    accA.x = accB.x + P1.x; accA.y = accB.y + P1.y;
    accA.z = accB.z + P1.z; accA.w = accB.w + P1.w;
    accB = P0;

    float* op = obase + rb * WW + col;

    #pragma unroll 4
    for (int i = 0; i < 16; i++) {
        // z = rb+1+i arrives; emit out row rb+i.
        fcur = fnext;
        fnext = ldrow(xp, rb + 2 + i, col, act);
        proc_row(tab8, tab1, g_pad, lane, fcur, P0, P1, P2);

        if (act) {
            float4 o;
            o.x = accA.x + P2.x;
            o.y = accA.y + P2.y;
            o.z = accA.z + P2.z;
            o.w = accA.w + P2.w;
            *(float4*)op = o;
        }
        op += WW;

        accA.x = accB.x + P1.x; accA.y = accB.y + P1.y;
        accA.z = accB.z + P1.z; accA.w = accB.w + P1.w;
        accB = P0;
    }
}

extern "C" void kernel_launch(void* const* d_in, const int* in_sizes, int n_in,
                              void* d_out, int out_size) {
    const float* x      = (const float*)d_in[0];
    const float* weight = (const float*)d_in[1];
    const float* lut    = (const float*)d_in[2];
    float* out          = (float*)d_out;

    build_table_kernel<<<C_, TABW>>>(weight, lut);
    conv_kernel<<<BATCH * C_, NTHR>>>(x, out);
}

// round 12
// speedup vs baseline: 1.5171x; 1.0716x over previous
#include <cuda_runtime.h>
#include <cuda_fp16.h>
#include <stdint.h>

#define C_     128
#define HH     112
#define WW     112
#define BATCH  8
#define TABW   512            // 511 valid entries + 1 pad (255 = zero-pixel)
#define NTHR   128            // 4 warps; warp = 14 out rows; lane<28 = 4 cols
#define HROWS  56             // rows per block (half channel)

// Per-channel packed tables:
// g_tab8[c*512+i] = half8 {t00,t01,t02,t10,t11,t12,t20,t21} for index i
// g_tab1[c*512+i] = float t22
__device__ uint4 g_tab8[C_ * TABW];
__device__ float g_tab1[C_ * TABW];

__global__ void build_table_kernel(const float* __restrict__ weight,
                                   const float* __restrict__ lut) {
    int c = blockIdx.x;
    int j = threadIdx.x;             // 512 threads, one entry each

    float v[9];
    #pragma unroll
    for (int k = 0; k < 9; k++) {
        float w  = weight[c * 9 + k];
        float t1 = rintf(w * 1000.0f);
        t1 = fminf(fmaxf(t1, -255.0f), 255.0f);
        int   i1 = (int)fabsf(t1);
        float s1 = (t1 > 0.0f) ? 1.0f : ((t1 < 0.0f) ? -1.0f : 0.0f);
        float val = 0.0f;
        if (j < 511) {
            int t2 = j - 255;
            int i2 = abs(t2);
            bool pos = (s1 > 0.0f && t2 > 0) || (s1 < 0.0f && t2 < 0);
            val = lut[i1 * 256 + i2] * (pos ? 1.0f : -1.0f) * (1.0f / 1000.0f);
        }
        v[k] = val;
    }
    __half2 p0 = __floats2half2_rn(v[0], v[1]);
    __half2 p1 = __floats2half2_rn(v[2], v[3]);
    __half2 p2 = __floats2half2_rn(v[4], v[5]);
    __half2 p3 = __floats2half2_rn(v[6], v[7]);
    uint4 q;
    q.x = *reinterpret_cast<uint32_t*>(&p0);
    q.y = *reinterpret_cast<uint32_t*>(&p1);
    q.z = *reinterpret_cast<uint32_t*>(&p2);
    q.w = *reinterpret_cast<uint32_t*>(&p3);
    g_tab8[(size_t)c * TABW + j] = q;
    g_tab1[(size_t)c * TABW + j] = v[8];
}

__device__ __forceinline__ float h_lo(uint32_t u) {
    __half2 h = *reinterpret_cast<__half2*>(&u);
    return __low2float(h);
}
__device__ __forceinline__ float h_hi(uint32_t u) {
    __half2 h = *reinterpret_cast<__half2*>(&u);
    return __high2float(h);
}

__device__ __forceinline__ float4 ldrow(const float* __restrict__ xp, int r, int col, bool act) {
    if (act && r >= 0 && r < HH)
        return *(const float4*)(xp + r * WW + col);
    return make_float4(0.0f, 0.0f, 0.0f, 0.0f);
}

// One idx row z: 4 LDS.128 + 4 LDS.32 gathers, halos via value-shuffle.
// Yields three 4-wide partial rows: P0 -> out z+1, P1 -> out z, P2 -> out z-1.
__device__ __forceinline__ void proc_row(const uint4* __restrict__ tab8,
                                         const float* __restrict__ tab1,
                                         uint4 g_pad, int lane, float4 f,
                                         float4& P0, float4& P1, float4& P2) {
    int i0 = min(max(__float2int_rn(f.x), -255), 255) + 255;
    int i1 = min(max(__float2int_rn(f.y), -255), 255) + 255;
    int i2 = min(max(__float2int_rn(f.z), -255), 255) + 255;
    int i3 = min(max(__float2int_rn(f.w), -255), 255) + 255;

    // hr index (right halo) for the t22 scalar gather.
    uint32_t hr = (uint32_t)__shfl_down_sync(0xffffffffu, i0, 1);
    // lane 27's source (lane 28) quantized a zero row -> 255 (pad). OK.

    uint4 g1 = tab8[i0], g2 = tab8[i1], g3 = tab8[i2], g4 = tab8[i3];
    float f0 = tab1[i1], f1 = tab1[i2], f2 = tab1[i3], f3 = tab1[hr];

    // Left halo entry g0 = left lane's g4 (3 words needed).
    uint32_t s4x = __shfl_up_sync(0xffffffffu, g4.x, 1);
    uint32_t s4y = __shfl_up_sync(0xffffffffu, g4.y, 1);
    uint32_t s4w = __shfl_up_sync(0xffffffffu, g4.w, 1);
    if (lane == 0) { s4x = g_pad.x; s4y = g_pad.y; s4w = g_pad.w; }
    // Right halo entry g5 = right lane's g1 (2 words needed).
    uint32_t s1y = __shfl_down_sync(0xffffffffu, g1.y, 1);
    uint32_t s1z = __shfl_down_sync(0xffffffffu, g1.z, 1);
    // lane 27 receives lane 28's pad gathers (idx 255). OK.

    P0.x = h_lo(s4x)  + h_hi(g1.x) + h_lo(g2.y);
    P0.y = h_lo(g1.x) + h_hi(g2.x) + h_lo(g3.y);
    P0.z = h_lo(g2.x) + h_hi(g3.x) + h_lo(g4.y);
    P0.w = h_lo(g3.x) + h_hi(g4.x) + h_lo(s1y);

    P1.x = h_hi(s4y)  + h_lo(g1.z) + h_hi(g2.z);
    P1.y = h_hi(g1.y) + h_lo(g2.z) + h_hi(g3.z);
    P1.z = h_hi(g2.y) + h_lo(g3.z) + h_hi(g4.z);
    P1.w = h_hi(g3.y) + h_lo(g4.z) + h_hi(s1z);

    P2.x = h_lo(s4w)  + h_hi(g1.w) + f0;
    P2.y = h_lo(g1.w) + h_hi(g2.w) + f1;
    P2.z = h_lo(g2.w) + h_hi(g3.w) + f2;
    P2.w = h_lo(g3.w) + h_hi(g4.w) + f3;
}

__global__ __launch_bounds__(NTHR, 12) void conv_kernel(const float* __restrict__ x,
                                                        float* __restrict__ out) {
    __shared__ uint4 tab8[TABW];                 // 8192 B
    __shared__ float tab1[TABW];                 // 2048 B

    int bid  = blockIdx.x;                 // (b, c, half)
    int half = bid & 1;
    int c    = (bid >> 1) & (C_ - 1);
    int b    = bid >> 8;
    int t    = threadIdx.x;

    // Stage this channel's tables once.
    {
        const uint4* ts = g_tab8 + (size_t)c * TABW;
        const float* fs = g_tab1 + (size_t)c * TABW;
        #pragma unroll
        for (int i = t; i < TABW; i += NTHR) {
            tab8[i] = ts[i];
            tab1[i] = fs[i];
        }
    }
    __syncthreads();

    int warp = t >> 5;
    int lane = t & 31;
    bool act = lane < 28;
    int col  = 4 * lane;
    int rb   = half * HROWS + warp * 14;   // 4 warps x 14 rows = 56 per block

    const float* xp = x + ((size_t)(b * C_ + c)) * (HH * WW);
    float* obase    = out + ((size_t)(b * C_ + c)) * (HH * WW);

    uint4 g_pad = tab8[255];               // zero-pixel entry (uniform)

    float4 P0, P1, P2;
    float4 accA = make_float4(0.f, 0.f, 0.f, 0.f);
    float4 accB = make_float4(0.f, 0.f, 0.f, 0.f);

    float4 fcur  = ldrow(xp, rb - 1, col, act);
    float4 fnext = ldrow(xp, rb, col, act);

    // Peel z = rb-1: accB = P0.
    proc_row(tab8, tab1, g_pad, lane, fcur, P0, P1, P2);
    accB = P0;

    // Peel z = rb: accA = accB + P1; accB = P0. (out[rb-1] not ours)
    fcur = fnext;
    fnext = ldrow(xp, rb + 1, col, act);
    proc_row(tab8, tab1, g_pad, lane, fcur, P0, P1, P2);
    accA.x = accB.x + P1.x; accA.y = accB.y + P1.y;
    accA.z = accB.z + P1.z; accA.w = accB.w + P1.w;
    accB = P0;

    float* op = obase + rb * WW + col;

    #pragma unroll 7
    for (int i = 0; i < 14; i++) {
        // z = rb+1+i arrives; emit out row rb+i.
        fcur = fnext;
        fnext = ldrow(xp, rb + 2 + i, col, act);
        proc_row(tab8, tab1, g_pad, lane, fcur, P0, P1, P2);

        if (act) {
            float4 o;
            o.x = accA.x + P2.x;
            o.y = accA.y + P2.y;
            o.z = accA.z + P2.z;
            o.w = accA.w + P2.w;
            *(float4*)op = o;
        }
        op += WW;

        accA.x = accB.x + P1.x; accA.y = accB.y + P1.y;
        accA.z = accB.z + P1.z; accA.w = accB.w + P1.w;
        accB = P0;
    }
}

extern "C" void kernel_launch(void* const* d_in, const int* in_sizes, int n_in,
                              void* d_out, int out_size) {
    const float* x      = (const float*)d_in[0];
    const float* weight = (const float*)d_in[1];
    const float* lut    = (const float*)d_in[2];
    float* out          = (float*)d_out;

    build_table_kernel<<<C_, TABW>>>(weight, lut);
    conv_kernel<<<BATCH * C_ * 2, NTHR>>>(x, out);
}